// round 15
// baseline (speedup 1.0000x reference)
#include <cuda_runtime.h>
#include <cuda_fp16.h>
#include <mma.h>
#include <math.h>

using namespace nvcuda;

#define NN 100000
#define MAXD 64
#define FIN 128
#define FHID 32
#define FOUT 16
#define EPSV 1e-5f
#define NSLOPE 0.2f

// ---------------- scratch ----------------
__device__ __half g_hA[NN * 64];
__device__ __half g_hB[NN * 64];
__device__ int   g_deg[NN];            // doubles as scatter cursor
__device__ int   g_csr[NN * MAXD];     // fixed-stride adjacency
__device__ float g_al[NN * 4];         // [als0, als1, ald0, ald1]

// ---------------- helpers ----------------
__device__ __forceinline__ float lrelu(float x) { return x > 0.f ? x : NSLOPE * x; }
__device__ __forceinline__ uint4 pack8(const float4& a, const float4& b) {
    union { __half2 h[4]; uint4 u; } pk;
    pk.h[0] = __floats2half2_rn(a.x, a.y);
    pk.h[1] = __floats2half2_rn(a.z, a.w);
    pk.h[2] = __floats2half2_rn(b.x, b.y);
    pk.h[3] = __floats2half2_rn(b.z, b.w);
    return pk.u;
}
__device__ __forceinline__ void unpack8(uint4 u, float4& a, float4& b) {
    union { uint4 u; __half2 h[4]; } pk; pk.u = u;
    float2 t0 = __half22float2(pk.h[0]);
    float2 t1 = __half22float2(pk.h[1]);
    float2 t2 = __half22float2(pk.h[2]);
    float2 t3 = __half22float2(pk.h[3]);
    a.x = t0.x; a.y = t0.y; a.z = t1.x; a.w = t1.y;
    b.x = t2.x; b.y = t2.y; b.z = t3.x; b.w = t3.y;
}
#define FMA4(acc, v, s) \
    acc.x = fmaf(v.x, s, acc.x); acc.y = fmaf(v.y, s, acc.y); \
    acc.z = fmaf(v.z, s, acc.z); acc.w = fmaf(v.w, s, acc.w);
#define ADD4(acc, v) \
    acc.x += v.x; acc.y += v.y; acc.z += v.z; acc.w += v.w;

// ---------------- adjacency build ----------------
__global__ void k_scatter(const int* __restrict__ src, const int* __restrict__ dst, int e) {
    int i = blockIdx.x * blockDim.x + threadIdx.x;
    if (i >= e) return;
    int d = dst[i];
    int pos = atomicAdd(&g_deg[d], 1);
    if (pos < MAXD) g_csr[d * MAXD + pos] = src[i];
}

// ---------------- unified tensor-core GEMM (ROWS rows/block, fp32 acc) ----------------
// INFLOAT: X fp32 -> staged half in smem. Else X half, wmma loads from global.
// DSCALE: scale row by rsqrt(deg+1).
// ALMODE 1 (F=64): per-head logits reduce xor 1,2. ALMODE 2 (F=32): reduce xor 1.
template <int K, int F, int ALMODE, int DSCALE, int INFLOAT, int ROWS>
__global__ void __launch_bounds__(256) k_gemm_tc(
        const void* __restrict__ Xv, const float* __restrict__ W,
        __half* __restrict__ Y,
        const float* __restrict__ a_s, const float* __restrict__ a_d, int n) {
    constexpr int NT = 256;
    constexpr int RT = ROWS / 16;
    constexpr int CT = F / 16;
    constexpr int CG = F / 8;
    constexpr int LDC = F + 4;
    constexpr int LDX = K + 8;
    __shared__ __half Wh[K * F];
    __shared__ __align__(16) float Acc[ROWS * LDC];
    __shared__ __align__(16) __half Xsh[INFLOAT ? ROWS * LDX : 16];
    int tid = threadIdx.x;
    for (int i = tid; i < K * F; i += NT) Wh[i] = __float2half(W[i]);
    int row0 = blockIdx.x * ROWS;
    const __half* Asrc;
    int lda;
    if (INFLOAT) {
        const float* X = (const float*)Xv;
        for (int i = tid; i < ROWS * K / 2; i += NT) {
            int elem = i * 2;
            int r = elem / K, kk = elem % K;
            int gr = row0 + r;
            float2 v = make_float2(0.f, 0.f);
            if (gr < n) v = *(const float2*)&X[(long)gr * K + kk];
            *(__half2*)&Xsh[r * LDX + kk] = __floats2half2_rn(v.x, v.y);
        }
        Asrc = Xsh; lda = LDX;
    } else {
        Asrc = (const __half*)Xv + (long)row0 * K; lda = K;
    }
    __syncthreads();
    int wid = tid >> 5;
#pragma unroll
    for (int p = wid; p < RT * CT; p += NT / 32) {
        int wr = p / CT, wc = p % CT;
        wmma::fragment<wmma::accumulator, 16, 16, 16, float> cfrag;
        wmma::fill_fragment(cfrag, 0.f);
        wmma::fragment<wmma::matrix_a, 16, 16, 16, __half, wmma::row_major> afrag;
        wmma::fragment<wmma::matrix_b, 16, 16, 16, __half, wmma::row_major> bfrag;
#pragma unroll
        for (int k = 0; k < K / 16; ++k) {
            wmma::load_matrix_sync(afrag, Asrc + (long)(wr * 16) * lda + k * 16, lda);
            wmma::load_matrix_sync(bfrag, Wh + k * 16 * F + wc * 16, F);
            wmma::mma_sync(cfrag, afrag, bfrag, cfrag);
        }
        wmma::store_matrix_sync(Acc + wr * 16 * LDC + wc * 16, cfrag, LDC, wmma::mem_row_major);
    }
    __syncthreads();

    // epilogue: thread owns 8 cols of a row; uniform loop (shuffles stay converged)
    int cg = tid % CG;
#pragma unroll
    for (int row = tid / CG; row < ROWS; row += NT / CG) {
        int gr = row0 + row;
        bool ok = gr < n;
        float4 aA = *(const float4*)&Acc[row * LDC + cg * 8];
        float4 aB = *(const float4*)&Acc[row * LDC + cg * 8 + 4];
        if (ok) {
            float4 oA = aA, oB = aB;
            if (DSCALE) {
                float dv = rsqrtf((float)(__ldg(&g_deg[gr]) + 1));
                oA.x *= dv; oA.y *= dv; oA.z *= dv; oA.w *= dv;
                oB.x *= dv; oB.y *= dv; oB.z *= dv; oB.w *= dv;
            }
            ((uint4*)Y)[(long)gr * CG + cg] = pack8(oA, oB);
        }
        if (ALMODE) {
            int col0 = cg * 8;
            float4 sA = *(const float4*)&a_s[col0];
            float4 sB = *(const float4*)&a_s[col0 + 4];
            float4 dA = *(const float4*)&a_d[col0];
            float4 dB = *(const float4*)&a_d[col0 + 4];
            float s = aA.x * sA.x + aA.y * sA.y + aA.z * sA.z + aA.w * sA.w
                    + aB.x * sB.x + aB.y * sB.y + aB.z * sB.z + aB.w * sB.w;
            float d = aA.x * dA.x + aA.y * dA.y + aA.z * dA.z + aA.w * dA.w
                    + aB.x * dB.x + aB.y * dB.y + aB.z * dB.z + aB.w * dB.w;
            if (ALMODE == 1) {        // CG=8: head = cg>>2
                s += __shfl_xor_sync(0xffffffffu, s, 1);
                d += __shfl_xor_sync(0xffffffffu, d, 1);
                s += __shfl_xor_sync(0xffffffffu, s, 2);
                d += __shfl_xor_sync(0xffffffffu, d, 2);
                int head = cg >> 2;
                if (ok && (cg & 3) == 0) {
                    g_al[gr * 4 + head] = s;
                    g_al[gr * 4 + 2 + head] = d;
                }
            } else {                  // CG=4: head = cg>>1
                s += __shfl_xor_sync(0xffffffffu, s, 1);
                d += __shfl_xor_sync(0xffffffffu, d, 1);
                int head = cg >> 1;
                if (ok && (cg & 1) == 0) {
                    g_al[gr * 4 + head] = s;
                    g_al[gr * 4 + 2 + head] = d;
                }
            }
        }
    }
}

// ---------------- GCN gather: 4 lanes/node ----------------
__global__ void k_gcn_agg(const __half* __restrict__ h, __half* __restrict__ out,
                          const float* __restrict__ bias,
                          const float* __restrict__ bg, const float* __restrict__ bb,
                          const float* __restrict__ bm, const float* __restrict__ bv, int n) {
    int t = blockIdx.x * blockDim.x + threadIdx.x;
    int w = t >> 2, c = t & 3;
    if (w >= n) return;
    const uint4* h4 = (const uint4*)h;
    int deg = __ldg(&g_deg[w]);
    int base = w * MAXD;
    float dd = rsqrtf((float)(deg + 1));
    float4 accA, accB;
    unpack8(__ldg(&h4[(long)w * 4 + c]), accA, accB);  // self (pre-scaled)
#pragma unroll 8
    for (int j = 0; j < deg; ++j) {
        int s = __ldg(&g_csr[base + j]);
        float4 vA, vB;
        unpack8(__ldg(&h4[(long)s * 4 + c]), vA, vB);
        ADD4(accA, vA);
        ADD4(accB, vB);
    }
    const float4* b4 = (const float4*)bias;
    const float4* g4 = (const float4*)bg;
    const float4* bb4 = (const float4*)bb;
    const float4* m4 = (const float4*)bm;
    const float4* v4 = (const float4*)bv;
    float4 oA, oB;
    {
        float4 bi = __ldg(&b4[c * 2]), gg = __ldg(&g4[c * 2]), bbv = __ldg(&bb4[c * 2]);
        float4 mm = __ldg(&m4[c * 2]), vv = __ldg(&v4[c * 2]);
        oA.x = fmaxf((accA.x * dd + bi.x - mm.x) * (gg.x * rsqrtf(vv.x + EPSV)) + bbv.x, 0.f);
        oA.y = fmaxf((accA.y * dd + bi.y - mm.y) * (gg.y * rsqrtf(vv.y + EPSV)) + bbv.y, 0.f);
        oA.z = fmaxf((accA.z * dd + bi.z - mm.z) * (gg.z * rsqrtf(vv.z + EPSV)) + bbv.z, 0.f);
        oA.w = fmaxf((accA.w * dd + bi.w - mm.w) * (gg.w * rsqrtf(vv.w + EPSV)) + bbv.w, 0.f);
    }
    {
        float4 bi = __ldg(&b4[c * 2 + 1]), gg = __ldg(&g4[c * 2 + 1]), bbv = __ldg(&bb4[c * 2 + 1]);
        float4 mm = __ldg(&m4[c * 2 + 1]), vv = __ldg(&v4[c * 2 + 1]);
        oB.x = fmaxf((accB.x * dd + bi.x - mm.x) * (gg.x * rsqrtf(vv.x + EPSV)) + bbv.x, 0.f);
        oB.y = fmaxf((accB.y * dd + bi.y - mm.y) * (gg.y * rsqrtf(vv.y + EPSV)) + bbv.y, 0.f);
        oB.z = fmaxf((accB.z * dd + bi.z - mm.z) * (gg.z * rsqrtf(vv.z + EPSV)) + bbv.z, 0.f);
        oB.w = fmaxf((accB.w * dd + bi.w - mm.w) * (gg.w * rsqrtf(vv.w + EPSV)) + bbv.w, 0.f);
    }
    ((uint4*)out)[(long)w * 4 + c] = pack8(oA, oB);
}

// ---------------- GAT1 gather: 8 lanes/node (head = c>>2) ----------------
__global__ void k_gat1_agg(const __half* __restrict__ hg, __half* __restrict__ out,
                           const float* __restrict__ bias, int n) {
    int t = blockIdx.x * blockDim.x + threadIdx.x;
    int w = t >> 3, c = t & 7;
    if (w >= n) return;
    const uint4* hg4 = (const uint4*)hg;
    int deg = __ldg(&g_deg[w]);
    int base = w * MAXD;
    float ald0 = g_al[w * 4 + 2], ald1 = g_al[w * 4 + 3];
    float w0 = __expf(lrelu(g_al[w * 4 + 0] + ald0));
    float w1 = __expf(lrelu(g_al[w * 4 + 1] + ald1));
    float s0 = w0, s1 = w1;
    int head = c >> 2;
    float selfw = head ? w1 : w0;
    float4 accA, accB;
    unpack8(__ldg(&hg4[(long)w * 8 + c]), accA, accB);
    accA.x *= selfw; accA.y *= selfw; accA.z *= selfw; accA.w *= selfw;
    accB.x *= selfw; accB.y *= selfw; accB.z *= selfw; accB.w *= selfw;
#pragma unroll 4
    for (int j = 0; j < deg; ++j) {
        int s = __ldg(&g_csr[base + j]);
        float2 av = *(const float2*)&g_al[s * 4];
        float a0 = __expf(lrelu(av.x + ald0));
        float a1 = __expf(lrelu(av.y + ald1));
        s0 += a0; s1 += a1;
        float aw = head ? a1 : a0;
        float4 vA, vB;
        unpack8(__ldg(&hg4[(long)s * 8 + c]), vA, vB);
        FMA4(accA, vA, aw);
        FMA4(accB, vB, aw);
    }
    float iown = 0.5f / (head ? s1 : s0);
    float ioth = 0.5f / (head ? s0 : s1);
    float4 pA, pB;
    pA.x = __shfl_xor_sync(0xffffffffu, accA.x, 4);
    pA.y = __shfl_xor_sync(0xffffffffu, accA.y, 4);
    pA.z = __shfl_xor_sync(0xffffffffu, accA.z, 4);
    pA.w = __shfl_xor_sync(0xffffffffu, accA.w, 4);
    pB.x = __shfl_xor_sync(0xffffffffu, accB.x, 4);
    pB.y = __shfl_xor_sync(0xffffffffu, accB.y, 4);
    pB.z = __shfl_xor_sync(0xffffffffu, accB.z, 4);
    pB.w = __shfl_xor_sync(0xffffffffu, accB.w, 4);
    if (head == 0) {
        const float4* b4 = (const float4*)bias;
        float4 biA = __ldg(&b4[c * 2]), biB = __ldg(&b4[c * 2 + 1]);
        float4 oA, oB;
        oA.x = fmaxf(accA.x * iown + pA.x * ioth + biA.x, 0.f);
        oA.y = fmaxf(accA.y * iown + pA.y * ioth + biA.y, 0.f);
        oA.z = fmaxf(accA.z * iown + pA.z * ioth + biA.z, 0.f);
        oA.w = fmaxf(accA.w * iown + pA.w * ioth + biA.w, 0.f);
        oB.x = fmaxf(accB.x * iown + pB.x * ioth + biB.x, 0.f);
        oB.y = fmaxf(accB.y * iown + pB.y * ioth + biB.y, 0.f);
        oB.z = fmaxf(accB.z * iown + pB.z * ioth + biB.z, 0.f);
        oB.w = fmaxf(accB.w * iown + pB.w * ioth + biB.w, 0.f);
        ((uint4*)out)[(long)w * 4 + c] = pack8(oA, oB);
    }
}

// ---------------- GAT2 gather: 4 lanes/node (head = c>>1) + log_softmax ----------------
__global__ void k_gat2_agg(const __half* __restrict__ hg, float* __restrict__ out,
                           const float* __restrict__ bias, int n) {
    int t = blockIdx.x * blockDim.x + threadIdx.x;
    int w = t >> 2, c = t & 3;
    if (w >= n) return;
    const uint4* hg4 = (const uint4*)hg;
    int deg = __ldg(&g_deg[w]);
    int base = w * MAXD;
    float ald0 = g_al[w * 4 + 2], ald1 = g_al[w * 4 + 3];
    float w0 = __expf(lrelu(g_al[w * 4 + 0] + ald0));
    float w1 = __expf(lrelu(g_al[w * 4 + 1] + ald1));
    float s0 = w0, s1 = w1;
    int head = c >> 1;
    float selfw = head ? w1 : w0;
    float4 accA, accB;
    unpack8(__ldg(&hg4[(long)w * 4 + c]), accA, accB);
    accA.x *= selfw; accA.y *= selfw; accA.z *= selfw; accA.w *= selfw;
    accB.x *= selfw; accB.y *= selfw; accB.z *= selfw; accB.w *= selfw;
#pragma unroll 4
    for (int j = 0; j < deg; ++j) {
        int s = __ldg(&g_csr[base + j]);
        float2 av = *(const float2*)&g_al[s * 4];
        float a0 = __expf(lrelu(av.x + ald0));
        float a1 = __expf(lrelu(av.y + ald1));
        s0 += a0; s1 += a1;
        float aw = head ? a1 : a0;
        float4 vA, vB;
        unpack8(__ldg(&hg4[(long)s * 4 + c]), vA, vB);
        FMA4(accA, vA, aw);
        FMA4(accB, vB, aw);
    }
    float iown = 0.5f / (head ? s1 : s0);
    float ioth = 0.5f / (head ? s0 : s1);
    float4 pA, pB;
    pA.x = __shfl_xor_sync(0xffffffffu, accA.x, 2);
    pA.y = __shfl_xor_sync(0xffffffffu, accA.y, 2);
    pA.z = __shfl_xor_sync(0xffffffffu, accA.z, 2);
    pA.w = __shfl_xor_sync(0xffffffffu, accA.w, 2);
    pB.x = __shfl_xor_sync(0xffffffffu, accB.x, 2);
    pB.y = __shfl_xor_sync(0xffffffffu, accB.y, 2);
    pB.z = __shfl_xor_sync(0xffffffffu, accB.z, 2);
    pB.w = __shfl_xor_sync(0xffffffffu, accB.w, 2);
    int blk = c & 1;
    const float4* b4 = (const float4*)bias;
    float4 biA = __ldg(&b4[blk * 2]), biB = __ldg(&b4[blk * 2 + 1]);
    float4 vA, vB;
    vA.x = accA.x * iown + pA.x * ioth + biA.x;
    vA.y = accA.y * iown + pA.y * ioth + biA.y;
    vA.z = accA.z * iown + pA.z * ioth + biA.z;
    vA.w = accA.w * iown + pA.w * ioth + biA.w;
    vB.x = accB.x * iown + pB.x * ioth + biB.x;
    vB.y = accB.y * iown + pB.y * ioth + biB.y;
    vB.z = accB.z * iown + pB.z * ioth + biB.z;
    vB.w = accB.w * iown + pB.w * ioth + biB.w;
    float mx = fmaxf(fmaxf(vA.x, vA.y), fmaxf(vA.z, vA.w));
    mx = fmaxf(mx, fmaxf(fmaxf(vB.x, vB.y), fmaxf(vB.z, vB.w)));
    mx = fmaxf(mx, __shfl_xor_sync(0xffffffffu, mx, 1));
    float se = __expf(vA.x - mx) + __expf(vA.y - mx) + __expf(vA.z - mx) + __expf(vA.w - mx)
             + __expf(vB.x - mx) + __expf(vB.y - mx) + __expf(vB.z - mx) + __expf(vB.w - mx);
    se += __shfl_xor_sync(0xffffffffu, se, 1);
    float ls = __logf(se) + mx;
    if (head == 0) {
        float4 oA, oB;
        oA.x = vA.x - ls; oA.y = vA.y - ls; oA.z = vA.z - ls; oA.w = vA.w - ls;
        oB.x = vB.x - ls; oB.y = vB.y - ls; oB.z = vB.z - ls; oB.w = vB.w - ls;
        ((float4*)out)[(long)w * 4 + blk * 2] = oA;
        ((float4*)out)[(long)w * 4 + blk * 2 + 1] = oB;
    }
}

// ---------------- host ----------------
static inline int cdiv(long a, int b) { return (int)((a + b - 1) / b); }

extern "C" void kernel_launch(void* const* d_in, const int* in_sizes, int n_in,
                              void* d_out, int out_size) {
    const float* x   = (const float*)d_in[0];
    const int*   ei  = (const int*)d_in[1];
    const float* g1W = (const float*)d_in[2];
    const float* g1b = (const float*)d_in[3];
    const float* b1g = (const float*)d_in[4];
    const float* b1b = (const float*)d_in[5];
    const float* b1m = (const float*)d_in[6];
    const float* b1v = (const float*)d_in[7];
    const float* a1W = (const float*)d_in[8];
    const float* a1s = (const float*)d_in[9];
    const float* a1d = (const float*)d_in[10];
    const float* a1b = (const float*)d_in[11];
    const float* g2W = (const float*)d_in[12];
    const float* g2b = (const float*)d_in[13];
    const float* b2g = (const float*)d_in[14];
    const float* b2b = (const float*)d_in[15];
    const float* b2m = (const float*)d_in[16];
    const float* b2v = (const float*)d_in[17];
    const float* a2W = (const float*)d_in[18];
    const float* a2s = (const float*)d_in[19];
    const float* a2d = (const float*)d_in[20];
    const float* a2b = (const float*)d_in[21];

    int n = in_sizes[0] / FIN;
    int e = in_sizes[1] / 2;
    const int* src = ei;
    const int* dst = ei + e;

    __half *pA, *pB;
    cudaGetSymbolAddress((void**)&pA, g_hA);
    cudaGetSymbolAddress((void**)&pB, g_hB);
    int* pDeg;
    cudaGetSymbolAddress((void**)&pDeg, g_deg);

    const int B = 256;

    // ---- adjacency build ----
    cudaMemsetAsync(pDeg, 0, (size_t)n * sizeof(int));
    k_scatter<<<cdiv(e, B), B>>>(src, dst, e);

    // ---- GCN1: tc GEMM K=128 F=32, fp32 input staged to half, ROWS=64 ----
    k_gemm_tc<FIN, FHID, 0, 1, 1, 64><<<cdiv(n, 64), 256>>>(x, g1W, pA, nullptr, nullptr, n);
    k_gcn_agg<<<cdiv((long)n * 4, B), B>>>(pA, pB, g1b, b1g, b1b, b1m, b1v, n);

    // ---- GAT1: tc GEMM K=32 F=64, ROWS=128 ----
    k_gemm_tc<FHID, 64, 1, 0, 0, 128><<<cdiv(n, 128), 256>>>(pB, a1W, pA, a1s, a1d, n);
    k_gat1_agg<<<cdiv((long)n * 8, B), B>>>(pA, pB, a1b, n);

    // ---- GCN2: tc GEMM K=32 F=32, ROWS=128 ----
    k_gemm_tc<FHID, FHID, 0, 1, 0, 128><<<cdiv(n, 128), 256>>>(pB, g2W, pA, nullptr, nullptr, n);
    k_gcn_agg<<<cdiv((long)n * 4, B), B>>>(pA, pB, g2b, b2g, b2b, b2m, b2v, n);

    // ---- GAT2: tc GEMM K=32 F=32, ROWS=128 + final log_softmax ----
    k_gemm_tc<FHID, FHID, 2, 0, 0, 128><<<cdiv(n, 128), 256>>>(pB, a2W, pA, a2s, a2d, n);
    k_gat2_agg<<<cdiv((long)n * 4, B), B>>>(pA, (float*)d_out, a2b, n);
}

// round 16
// speedup vs baseline: 1.0361x; 1.0361x over previous
#include <cuda_runtime.h>
#include <cuda_fp16.h>
#include <mma.h>
#include <math.h>

using namespace nvcuda;

#define NN 100000
#define MAXD 64
#define FIN 128
#define FHID 32
#define FOUT 16
#define EPSV 1e-5f
#define NSLOPE 0.2f

// ---------------- scratch ----------------
__device__ __half g_hA[NN * 64];
__device__ __half g_hB[NN * 64];
__device__ int   g_deg[NN];            // doubles as scatter cursor
__device__ int   g_csr[NN * MAXD];     // fixed-stride adjacency
__device__ float g_al[NN * 4];         // [als0, als1, ald0, ald1]

// ---------------- helpers ----------------
__device__ __forceinline__ float lrelu(float x) { return x > 0.f ? x : NSLOPE * x; }
__device__ __forceinline__ uint4 pack8(const float4& a, const float4& b) {
    union { __half2 h[4]; uint4 u; } pk;
    pk.h[0] = __floats2half2_rn(a.x, a.y);
    pk.h[1] = __floats2half2_rn(a.z, a.w);
    pk.h[2] = __floats2half2_rn(b.x, b.y);
    pk.h[3] = __floats2half2_rn(b.z, b.w);
    return pk.u;
}
__device__ __forceinline__ void unpack8(uint4 u, float4& a, float4& b) {
    union { uint4 u; __half2 h[4]; } pk; pk.u = u;
    float2 t0 = __half22float2(pk.h[0]);
    float2 t1 = __half22float2(pk.h[1]);
    float2 t2 = __half22float2(pk.h[2]);
    float2 t3 = __half22float2(pk.h[3]);
    a.x = t0.x; a.y = t0.y; a.z = t1.x; a.w = t1.y;
    b.x = t2.x; b.y = t2.y; b.z = t3.x; b.w = t3.y;
}
#define FMA4(acc, v, s) \
    acc.x = fmaf(v.x, s, acc.x); acc.y = fmaf(v.y, s, acc.y); \
    acc.z = fmaf(v.z, s, acc.z); acc.w = fmaf(v.w, s, acc.w);
#define ADD4(acc, v) \
    acc.x += v.x; acc.y += v.y; acc.z += v.z; acc.w += v.w;

// ---------------- adjacency build ----------------
__global__ void k_scatter(const int* __restrict__ src, const int* __restrict__ dst, int e) {
    int i = blockIdx.x * blockDim.x + threadIdx.x;
    if (i >= e) return;
    int d = dst[i];
    int pos = atomicAdd(&g_deg[d], 1);
    if (pos < MAXD) g_csr[d * MAXD + pos] = src[i];
}

// ---------------- unified tensor-core GEMM (64 rows/block, fp32 acc) ----------------
// X ALWAYS staged into smem (half) -> LDSM-based wmma loads, no redundant L1 traffic.
// INFLOAT: X fp32 (convert on stage). DSCALE: scale row by rsqrt(deg+1).
// ALMODE 1 (F=64): per-head logits reduce xor 1,2. ALMODE 2 (F=32): reduce xor 1.
template <int K, int F, int ALMODE, int DSCALE, int INFLOAT>
__global__ void __launch_bounds__(256) k_gemm_tc(
        const void* __restrict__ Xv, const float* __restrict__ W,
        __half* __restrict__ Y,
        const float* __restrict__ a_s, const float* __restrict__ a_d, int n) {
    constexpr int NT = 256;
    constexpr int ROWS = 64;
    constexpr int RT = ROWS / 16;
    constexpr int CT = F / 16;
    constexpr int CG = F / 8;
    constexpr int LDC = F + 4;
    constexpr int LDX = K + 8;       // halves; LDX*2 bytes divisible by 16
    __shared__ __half Wh[K * F];
    __shared__ __align__(16) float Acc[ROWS * LDC];
    __shared__ __align__(16) __half Xsh[ROWS * LDX];
    int tid = threadIdx.x;
    for (int i = tid; i < K * F; i += NT) Wh[i] = __float2half(W[i]);
    int row0 = blockIdx.x * ROWS;
    if (INFLOAT) {
        const float* X = (const float*)Xv;
        for (int i = tid; i < ROWS * K / 2; i += NT) {
            int elem = i * 2;
            int r = elem / K, kk = elem % K;
            int gr = row0 + r;
            float2 v = make_float2(0.f, 0.f);
            if (gr < n) v = *(const float2*)&X[(long)gr * K + kk];
            *(__half2*)&Xsh[r * LDX + kk] = __floats2half2_rn(v.x, v.y);
        }
    } else {
        const __half* X = (const __half*)Xv;
        constexpr int CPR = K / 8;   // uint4 chunks per row
        for (int i = tid; i < ROWS * CPR; i += NT) {
            int r = i / CPR, kc = (i % CPR) * 8;
            int gr = row0 + r;
            uint4 v = make_uint4(0u, 0u, 0u, 0u);
            if (gr < n) v = *(const uint4*)&X[(long)gr * K + kc];
            *(uint4*)&Xsh[r * LDX + kc] = v;
        }
    }
    __syncthreads();
    int wid = tid >> 5;
#pragma unroll
    for (int p = wid; p < RT * CT; p += NT / 32) {
        int wr = p / CT, wc = p % CT;
        wmma::fragment<wmma::accumulator, 16, 16, 16, float> cfrag;
        wmma::fill_fragment(cfrag, 0.f);
        wmma::fragment<wmma::matrix_a, 16, 16, 16, __half, wmma::row_major> afrag;
        wmma::fragment<wmma::matrix_b, 16, 16, 16, __half, wmma::row_major> bfrag;
#pragma unroll
        for (int k = 0; k < K / 16; ++k) {
            wmma::load_matrix_sync(afrag, Xsh + (wr * 16) * LDX + k * 16, LDX);
            wmma::load_matrix_sync(bfrag, Wh + k * 16 * F + wc * 16, F);
            wmma::mma_sync(cfrag, afrag, bfrag, cfrag);
        }
        wmma::store_matrix_sync(Acc + wr * 16 * LDC + wc * 16, cfrag, LDC, wmma::mem_row_major);
    }
    __syncthreads();

    // epilogue: thread owns 8 cols of a row; uniform loop (shuffles stay converged)
    int cg = tid % CG;
#pragma unroll
    for (int row = tid / CG; row < ROWS; row += NT / CG) {
        int gr = row0 + row;
        bool ok = gr < n;
        float4 aA = *(const float4*)&Acc[row * LDC + cg * 8];
        float4 aB = *(const float4*)&Acc[row * LDC + cg * 8 + 4];
        if (ok) {
            float4 oA = aA, oB = aB;
            if (DSCALE) {
                float dv = rsqrtf((float)(__ldg(&g_deg[gr]) + 1));
                oA.x *= dv; oA.y *= dv; oA.z *= dv; oA.w *= dv;
                oB.x *= dv; oB.y *= dv; oB.z *= dv; oB.w *= dv;
            }
            ((uint4*)Y)[(long)gr * CG + cg] = pack8(oA, oB);
        }
        if (ALMODE) {
            int col0 = cg * 8;
            float4 sA = *(const float4*)&a_s[col0];
            float4 sB = *(const float4*)&a_s[col0 + 4];
            float4 dA = *(const float4*)&a_d[col0];
            float4 dB = *(const float4*)&a_d[col0 + 4];
            float s = aA.x * sA.x + aA.y * sA.y + aA.z * sA.z + aA.w * sA.w
                    + aB.x * sB.x + aB.y * sB.y + aB.z * sB.z + aB.w * sB.w;
            float d = aA.x * dA.x + aA.y * dA.y + aA.z * dA.z + aA.w * dA.w
                    + aB.x * dB.x + aB.y * dB.y + aB.z * dB.z + aB.w * dB.w;
            if (ALMODE == 1) {        // CG=8: head = cg>>2
                s += __shfl_xor_sync(0xffffffffu, s, 1);
                d += __shfl_xor_sync(0xffffffffu, d, 1);
                s += __shfl_xor_sync(0xffffffffu, s, 2);
                d += __shfl_xor_sync(0xffffffffu, d, 2);
                int head = cg >> 2;
                if (ok && (cg & 3) == 0) {
                    g_al[gr * 4 + head] = s;
                    g_al[gr * 4 + 2 + head] = d;
                }
            } else {                  // CG=4: head = cg>>1
                s += __shfl_xor_sync(0xffffffffu, s, 1);
                d += __shfl_xor_sync(0xffffffffu, d, 1);
                int head = cg >> 1;
                if (ok && (cg & 1) == 0) {
                    g_al[gr * 4 + head] = s;
                    g_al[gr * 4 + 2 + head] = d;
                }
            }
        }
    }
}

// ---------------- GCN gather: 4 lanes/node ----------------
__global__ void k_gcn_agg(const __half* __restrict__ h, __half* __restrict__ out,
                          const float* __restrict__ bias,
                          const float* __restrict__ bg, const float* __restrict__ bb,
                          const float* __restrict__ bm, const float* __restrict__ bv, int n) {
    int t = blockIdx.x * blockDim.x + threadIdx.x;
    int w = t >> 2, c = t & 3;
    if (w >= n) return;
    const uint4* h4 = (const uint4*)h;
    int deg = __ldg(&g_deg[w]);
    int base = w * MAXD;
    float dd = rsqrtf((float)(deg + 1));
    float4 accA, accB;
    unpack8(__ldg(&h4[(long)w * 4 + c]), accA, accB);  // self (pre-scaled)
#pragma unroll 8
    for (int j = 0; j < deg; ++j) {
        int s = __ldg(&g_csr[base + j]);
        float4 vA, vB;
        unpack8(__ldg(&h4[(long)s * 4 + c]), vA, vB);
        ADD4(accA, vA);
        ADD4(accB, vB);
    }
    const float4* b4 = (const float4*)bias;
    const float4* g4 = (const float4*)bg;
    const float4* bb4 = (const float4*)bb;
    const float4* m4 = (const float4*)bm;
    const float4* v4 = (const float4*)bv;
    float4 oA, oB;
    {
        float4 bi = __ldg(&b4[c * 2]), gg = __ldg(&g4[c * 2]), bbv = __ldg(&bb4[c * 2]);
        float4 mm = __ldg(&m4[c * 2]), vv = __ldg(&v4[c * 2]);
        oA.x = fmaxf((accA.x * dd + bi.x - mm.x) * (gg.x * rsqrtf(vv.x + EPSV)) + bbv.x, 0.f);
        oA.y = fmaxf((accA.y * dd + bi.y - mm.y) * (gg.y * rsqrtf(vv.y + EPSV)) + bbv.y, 0.f);
        oA.z = fmaxf((accA.z * dd + bi.z - mm.z) * (gg.z * rsqrtf(vv.z + EPSV)) + bbv.z, 0.f);
        oA.w = fmaxf((accA.w * dd + bi.w - mm.w) * (gg.w * rsqrtf(vv.w + EPSV)) + bbv.w, 0.f);
    }
    {
        float4 bi = __ldg(&b4[c * 2 + 1]), gg = __ldg(&g4[c * 2 + 1]), bbv = __ldg(&bb4[c * 2 + 1]);
        float4 mm = __ldg(&m4[c * 2 + 1]), vv = __ldg(&v4[c * 2 + 1]);
        oB.x = fmaxf((accB.x * dd + bi.x - mm.x) * (gg.x * rsqrtf(vv.x + EPSV)) + bbv.x, 0.f);
        oB.y = fmaxf((accB.y * dd + bi.y - mm.y) * (gg.y * rsqrtf(vv.y + EPSV)) + bbv.y, 0.f);
        oB.z = fmaxf((accB.z * dd + bi.z - mm.z) * (gg.z * rsqrtf(vv.z + EPSV)) + bbv.z, 0.f);
        oB.w = fmaxf((accB.w * dd + bi.w - mm.w) * (gg.w * rsqrtf(vv.w + EPSV)) + bbv.w, 0.f);
    }
    ((uint4*)out)[(long)w * 4 + c] = pack8(oA, oB);
}

// ---------------- GAT1 gather: 8 lanes/node (head = c>>2) ----------------
__global__ void k_gat1_agg(const __half* __restrict__ hg, __half* __restrict__ out,
                           const float* __restrict__ bias, int n) {
    int t = blockIdx.x * blockDim.x + threadIdx.x;
    int w = t >> 3, c = t & 7;
    if (w >= n) return;
    const uint4* hg4 = (const uint4*)hg;
    int deg = __ldg(&g_deg[w]);
    int base = w * MAXD;
    float ald0 = g_al[w * 4 + 2], ald1 = g_al[w * 4 + 3];
    float w0 = __expf(lrelu(g_al[w * 4 + 0] + ald0));
    float w1 = __expf(lrelu(g_al[w * 4 + 1] + ald1));
    float s0 = w0, s1 = w1;
    int head = c >> 2;
    float selfw = head ? w1 : w0;
    float4 accA, accB;
    unpack8(__ldg(&hg4[(long)w * 8 + c]), accA, accB);
    accA.x *= selfw; accA.y *= selfw; accA.z *= selfw; accA.w *= selfw;
    accB.x *= selfw; accB.y *= selfw; accB.z *= selfw; accB.w *= selfw;
#pragma unroll 4
    for (int j = 0; j < deg; ++j) {
        int s = __ldg(&g_csr[base + j]);
        float2 av = *(const float2*)&g_al[s * 4];
        float a0 = __expf(lrelu(av.x + ald0));
        float a1 = __expf(lrelu(av.y + ald1));
        s0 += a0; s1 += a1;
        float aw = head ? a1 : a0;
        float4 vA, vB;
        unpack8(__ldg(&hg4[(long)s * 8 + c]), vA, vB);
        FMA4(accA, vA, aw);
        FMA4(accB, vB, aw);
    }
    float iown = 0.5f / (head ? s1 : s0);
    float ioth = 0.5f / (head ? s0 : s1);
    float4 pA, pB;
    pA.x = __shfl_xor_sync(0xffffffffu, accA.x, 4);
    pA.y = __shfl_xor_sync(0xffffffffu, accA.y, 4);
    pA.z = __shfl_xor_sync(0xffffffffu, accA.z, 4);
    pA.w = __shfl_xor_sync(0xffffffffu, accA.w, 4);
    pB.x = __shfl_xor_sync(0xffffffffu, accB.x, 4);
    pB.y = __shfl_xor_sync(0xffffffffu, accB.y, 4);
    pB.z = __shfl_xor_sync(0xffffffffu, accB.z, 4);
    pB.w = __shfl_xor_sync(0xffffffffu, accB.w, 4);
    if (head == 0) {
        const float4* b4 = (const float4*)bias;
        float4 biA = __ldg(&b4[c * 2]), biB = __ldg(&b4[c * 2 + 1]);
        float4 oA, oB;
        oA.x = fmaxf(accA.x * iown + pA.x * ioth + biA.x, 0.f);
        oA.y = fmaxf(accA.y * iown + pA.y * ioth + biA.y, 0.f);
        oA.z = fmaxf(accA.z * iown + pA.z * ioth + biA.z, 0.f);
        oA.w = fmaxf(accA.w * iown + pA.w * ioth + biA.w, 0.f);
        oB.x = fmaxf(accB.x * iown + pB.x * ioth + biB.x, 0.f);
        oB.y = fmaxf(accB.y * iown + pB.y * ioth + biB.y, 0.f);
        oB.z = fmaxf(accB.z * iown + pB.z * ioth + biB.z, 0.f);
        oB.w = fmaxf(accB.w * iown + pB.w * ioth + biB.w, 0.f);
        ((uint4*)out)[(long)w * 4 + c] = pack8(oA, oB);
    }
}

// ---------------- GAT2 gather: 4 lanes/node (head = c>>1) + log_softmax ----------------
__global__ void k_gat2_agg(const __half* __restrict__ hg, float* __restrict__ out,
                           const float* __restrict__ bias, int n) {
    int t = blockIdx.x * blockDim.x + threadIdx.x;
    int w = t >> 2, c = t & 3;
    if (w >= n) return;
    const uint4* hg4 = (const uint4*)hg;
    int deg = __ldg(&g_deg[w]);
    int base = w * MAXD;
    float ald0 = g_al[w * 4 + 2], ald1 = g_al[w * 4 + 3];
    float w0 = __expf(lrelu(g_al[w * 4 + 0] + ald0));
    float w1 = __expf(lrelu(g_al[w * 4 + 1] + ald1));
    float s0 = w0, s1 = w1;
    int head = c >> 1;
    float selfw = head ? w1 : w0;
    float4 accA, accB;
    unpack8(__ldg(&hg4[(long)w * 4 + c]), accA, accB);
    accA.x *= selfw; accA.y *= selfw; accA.z *= selfw; accA.w *= selfw;
    accB.x *= selfw; accB.y *= selfw; accB.z *= selfw; accB.w *= selfw;
#pragma unroll 4
    for (int j = 0; j < deg; ++j) {
        int s = __ldg(&g_csr[base + j]);
        float2 av = *(const float2*)&g_al[s * 4];
        float a0 = __expf(lrelu(av.x + ald0));
        float a1 = __expf(lrelu(av.y + ald1));
        s0 += a0; s1 += a1;
        float aw = head ? a1 : a0;
        float4 vA, vB;
        unpack8(__ldg(&hg4[(long)s * 4 + c]), vA, vB);
        FMA4(accA, vA, aw);
        FMA4(accB, vB, aw);
    }
    float iown = 0.5f / (head ? s1 : s0);
    float ioth = 0.5f / (head ? s0 : s1);
    float4 pA, pB;
    pA.x = __shfl_xor_sync(0xffffffffu, accA.x, 2);
    pA.y = __shfl_xor_sync(0xffffffffu, accA.y, 2);
    pA.z = __shfl_xor_sync(0xffffffffu, accA.z, 2);
    pA.w = __shfl_xor_sync(0xffffffffu, accA.w, 2);
    pB.x = __shfl_xor_sync(0xffffffffu, accB.x, 2);
    pB.y = __shfl_xor_sync(0xffffffffu, accB.y, 2);
    pB.z = __shfl_xor_sync(0xffffffffu, accB.z, 2);
    pB.w = __shfl_xor_sync(0xffffffffu, accB.w, 2);
    int blk = c & 1;
    const float4* b4 = (const float4*)bias;
    float4 biA = __ldg(&b4[blk * 2]), biB = __ldg(&b4[blk * 2 + 1]);
    float4 vA, vB;
    vA.x = accA.x * iown + pA.x * ioth + biA.x;
    vA.y = accA.y * iown + pA.y * ioth + biA.y;
    vA.z = accA.z * iown + pA.z * ioth + biA.z;
    vA.w = accA.w * iown + pA.w * ioth + biA.w;
    vB.x = accB.x * iown + pB.x * ioth + biB.x;
    vB.y = accB.y * iown + pB.y * ioth + biB.y;
    vB.z = accB.z * iown + pB.z * ioth + biB.z;
    vB.w = accB.w * iown + pB.w * ioth + biB.w;
    float mx = fmaxf(fmaxf(vA.x, vA.y), fmaxf(vA.z, vA.w));
    mx = fmaxf(mx, fmaxf(fmaxf(vB.x, vB.y), fmaxf(vB.z, vB.w)));
    mx = fmaxf(mx, __shfl_xor_sync(0xffffffffu, mx, 1));
    float se = __expf(vA.x - mx) + __expf(vA.y - mx) + __expf(vA.z - mx) + __expf(vA.w - mx)
             + __expf(vB.x - mx) + __expf(vB.y - mx) + __expf(vB.z - mx) + __expf(vB.w - mx);
    se += __shfl_xor_sync(0xffffffffu, se, 1);
    float ls = __logf(se) + mx;
    if (head == 0) {
        float4 oA, oB;
        oA.x = vA.x - ls; oA.y = vA.y - ls; oA.z = vA.z - ls; oA.w = vA.w - ls;
        oB.x = vB.x - ls; oB.y = vB.y - ls; oB.z = vB.z - ls; oB.w = vB.w - ls;
        ((float4*)out)[(long)w * 4 + blk * 2] = oA;
        ((float4*)out)[(long)w * 4 + blk * 2 + 1] = oB;
    }
}

// ---------------- host ----------------
static inline int cdiv(long a, int b) { return (int)((a + b - 1) / b); }

extern "C" void kernel_launch(void* const* d_in, const int* in_sizes, int n_in,
                              void* d_out, int out_size) {
    const float* x   = (const float*)d_in[0];
    const int*   ei  = (const int*)d_in[1];
    const float* g1W = (const float*)d_in[2];
    const float* g1b = (const float*)d_in[3];
    const float* b1g = (const float*)d_in[4];
    const float* b1b = (const float*)d_in[5];
    const float* b1m = (const float*)d_in[6];
    const float* b1v = (const float*)d_in[7];
    const float* a1W = (const float*)d_in[8];
    const float* a1s = (const float*)d_in[9];
    const float* a1d = (const float*)d_in[10];
    const float* a1b = (const float*)d_in[11];
    const float* g2W = (const float*)d_in[12];
    const float* g2b = (const float*)d_in[13];
    const float* b2g = (const float*)d_in[14];
    const float* b2b = (const float*)d_in[15];
    const float* b2m = (const float*)d_in[16];
    const float* b2v = (const float*)d_in[17];
    const float* a2W = (const float*)d_in[18];
    const float* a2s = (const float*)d_in[19];
    const float* a2d = (const float*)d_in[20];
    const float* a2b = (const float*)d_in[21];

    int n = in_sizes[0] / FIN;
    int e = in_sizes[1] / 2;
    const int* src = ei;
    const int* dst = ei + e;

    __half *pA, *pB;
    cudaGetSymbolAddress((void**)&pA, g_hA);
    cudaGetSymbolAddress((void**)&pB, g_hB);
    int* pDeg;
    cudaGetSymbolAddress((void**)&pDeg, g_deg);

    const int B = 256;

    // ---- adjacency build ----
    cudaMemsetAsync(pDeg, 0, (size_t)n * sizeof(int));
    k_scatter<<<cdiv(e, B), B>>>(src, dst, e);

    // ---- GCN1: tc GEMM K=128 F=32, fp32 input staged to half ----
    k_gemm_tc<FIN, FHID, 0, 1, 1><<<cdiv(n, 64), 256>>>(x, g1W, pA, nullptr, nullptr, n);
    k_gcn_agg<<<cdiv((long)n * 4, B), B>>>(pA, pB, g1b, b1g, b1b, b1m, b1v, n);

    // ---- GAT1: tc GEMM K=32 F=64, smem-staged A ----
    k_gemm_tc<FHID, 64, 1, 0, 0><<<cdiv(n, 64), 256>>>(pB, a1W, pA, a1s, a1d, n);
    k_gat1_agg<<<cdiv((long)n * 8, B), B>>>(pA, pB, a1b, n);

    // ---- GCN2: tc GEMM K=32 F=32, smem-staged A ----
    k_gemm_tc<FHID, FHID, 0, 1, 0><<<cdiv(n, 64), 256>>>(pB, g2W, pA, nullptr, nullptr, n);
    k_gcn_agg<<<cdiv((long)n * 4, B), B>>>(pA, pB, g2b, b2g, b2b, b2m, b2v, n);

    // ---- GAT2: tc GEMM K=32 F=32, smem-staged A + final log_softmax ----
    k_gemm_tc<FHID, FHID, 2, 0, 0><<<cdiv(n, 64), 256>>>(pB, a2W, pA, a2s, a2d, n);
    k_gat2_agg<<<cdiv((long)n * 4, B), B>>>(pA, (float*)d_out, a2b, n);
}

// round 17
// speedup vs baseline: 1.1224x; 1.0833x over previous
#include <cuda_runtime.h>
#include <cuda_fp16.h>
#include <mma.h>
#include <math.h>

using namespace nvcuda;

#define NN 100000
#define MAXD 64
#define FIN 128
#define FHID 32
#define FOUT 16
#define EPSV 1e-5f
#define NSLOPE 0.2f

// half weight cache offsets: GCN1 4096, GAT1 2048, GCN2 1024, GAT2 1024
#define WOFF_G1 0
#define WOFF_A1 4096
#define WOFF_G2 6144
#define WOFF_A2 7168

// ---------------- scratch ----------------
__device__ __half g_hA[NN * 64];
__device__ __half g_hB[NN * 64];
__device__ __half g_Wh[8192];
__device__ int   g_deg[NN];            // doubles as scatter cursor
__device__ int   g_csr[NN * MAXD];     // fixed-stride adjacency
__device__ float g_al[NN * 4];         // [als0, als1, ald0, ald1]

// ---------------- helpers ----------------
__device__ __forceinline__ float lrelu(float x) { return x > 0.f ? x : NSLOPE * x; }
__device__ __forceinline__ uint4 pack8(const float4& a, const float4& b) {
    union { __half2 h[4]; uint4 u; } pk;
    pk.h[0] = __floats2half2_rn(a.x, a.y);
    pk.h[1] = __floats2half2_rn(a.z, a.w);
    pk.h[2] = __floats2half2_rn(b.x, b.y);
    pk.h[3] = __floats2half2_rn(b.z, b.w);
    return pk.u;
}
__device__ __forceinline__ void unpack8(uint4 u, float4& a, float4& b) {
    union { uint4 u; __half2 h[4]; } pk; pk.u = u;
    float2 t0 = __half22float2(pk.h[0]);
    float2 t1 = __half22float2(pk.h[1]);
    float2 t2 = __half22float2(pk.h[2]);
    float2 t3 = __half22float2(pk.h[3]);
    a.x = t0.x; a.y = t0.y; a.z = t1.x; a.w = t1.y;
    b.x = t2.x; b.y = t2.y; b.z = t3.x; b.w = t3.y;
}
#define FMA4(acc, v, s) \
    acc.x = fmaf(v.x, s, acc.x); acc.y = fmaf(v.y, s, acc.y); \
    acc.z = fmaf(v.z, s, acc.z); acc.w = fmaf(v.w, s, acc.w);
#define ADD4(acc, v) \
    acc.x += v.x; acc.y += v.y; acc.z += v.z; acc.w += v.w;

// ---------------- weight conversion (once per launch) ----------------
__global__ void k_cvtW(const float* __restrict__ w1, const float* __restrict__ w2,
                       const float* __restrict__ w3, const float* __restrict__ w4) {
    int i = blockIdx.x * blockDim.x + threadIdx.x;
    if (i < 4096) g_Wh[WOFF_G1 + i] = __float2half(w1[i]);
    else if (i < 6144) g_Wh[WOFF_A1 + i - 4096] = __float2half(w2[i - 4096]);
    else if (i < 7168) g_Wh[WOFF_G2 + i - 6144] = __float2half(w3[i - 6144]);
    else if (i < 8192) g_Wh[WOFF_A2 + i - 7168] = __float2half(w4[i - 7168]);
}

// ---------------- adjacency build ----------------
__global__ void k_scatter(const int* __restrict__ src, const int* __restrict__ dst, int e) {
    int i = blockIdx.x * blockDim.x + threadIdx.x;
    if (i >= e) return;
    int d = dst[i];
    int pos = atomicAdd(&g_deg[d], 1);
    if (pos < MAXD) g_csr[d * MAXD + pos] = src[i];
}

// ---------------- unified tensor-core GEMM (64 rows/block, fp32 acc) ----------------
// A staged in smem (half); B fragments load straight from global half W (L1-hot).
// INFLOAT: X fp32 (convert on stage). DSCALE: scale row by rsqrt(deg+1).
// ALMODE 1 (F=64): per-head logits reduce xor 1,2. ALMODE 2 (F=32): reduce xor 1.
template <int K, int F, int ALMODE, int DSCALE, int INFLOAT>
__global__ void __launch_bounds__(256) k_gemm_tc(
        const void* __restrict__ Xv, const __half* __restrict__ Whg,
        __half* __restrict__ Y,
        const float* __restrict__ a_s, const float* __restrict__ a_d, int n) {
    constexpr int NT = 256;
    constexpr int ROWS = 64;
    constexpr int RT = ROWS / 16;
    constexpr int CT = F / 16;
    constexpr int CG = F / 8;
    constexpr int LDC = F + 4;
    constexpr int LDX = K + 8;       // halves; LDX even -> 16B-aligned rows
    __shared__ __align__(16) float Acc[ROWS * LDC];
    __shared__ __align__(16) __half Xsh[ROWS * LDX];
    int tid = threadIdx.x;
    int row0 = blockIdx.x * ROWS;
    if (INFLOAT) {
        const float* X = (const float*)Xv;
        for (int i = tid; i < ROWS * K / 4; i += NT) {
            int elem = i * 4;
            int r = elem / K, kk = elem % K;
            int gr = row0 + r;
            float4 v = make_float4(0.f, 0.f, 0.f, 0.f);
            if (gr < n) v = *(const float4*)&X[(long)gr * K + kk];
            *(__half2*)&Xsh[r * LDX + kk] = __floats2half2_rn(v.x, v.y);
            *(__half2*)&Xsh[r * LDX + kk + 2] = __floats2half2_rn(v.z, v.w);
        }
    } else {
        const __half* X = (const __half*)Xv;
        constexpr int CPR = K / 8;   // uint4 chunks per row
        for (int i = tid; i < ROWS * CPR; i += NT) {
            int r = i / CPR, kc = (i % CPR) * 8;
            int gr = row0 + r;
            uint4 v = make_uint4(0u, 0u, 0u, 0u);
            if (gr < n) v = *(const uint4*)&X[(long)gr * K + kc];
            *(uint4*)&Xsh[r * LDX + kc] = v;
        }
    }
    __syncthreads();
    int wid = tid >> 5;
#pragma unroll
    for (int p = wid; p < RT * CT; p += NT / 32) {
        int wr = p / CT, wc = p % CT;
        wmma::fragment<wmma::accumulator, 16, 16, 16, float> cfrag;
        wmma::fill_fragment(cfrag, 0.f);
        wmma::fragment<wmma::matrix_a, 16, 16, 16, __half, wmma::row_major> afrag;
        wmma::fragment<wmma::matrix_b, 16, 16, 16, __half, wmma::row_major> bfrag;
#pragma unroll
        for (int k = 0; k < K / 16; ++k) {
            wmma::load_matrix_sync(afrag, Xsh + (wr * 16) * LDX + k * 16, LDX);
            wmma::load_matrix_sync(bfrag, Whg + k * 16 * F + wc * 16, F);
            wmma::mma_sync(cfrag, afrag, bfrag, cfrag);
        }
        wmma::store_matrix_sync(Acc + wr * 16 * LDC + wc * 16, cfrag, LDC, wmma::mem_row_major);
    }
    __syncthreads();

    // epilogue: thread owns 8 cols of a row; uniform loop (shuffles stay converged)
    int cg = tid % CG;
#pragma unroll
    for (int row = tid / CG; row < ROWS; row += NT / CG) {
        int gr = row0 + row;
        bool ok = gr < n;
        float4 aA = *(const float4*)&Acc[row * LDC + cg * 8];
        float4 aB = *(const float4*)&Acc[row * LDC + cg * 8 + 4];
        if (ok) {
            float4 oA = aA, oB = aB;
            if (DSCALE) {
                float dv = rsqrtf((float)(__ldg(&g_deg[gr]) + 1));
                oA.x *= dv; oA.y *= dv; oA.z *= dv; oA.w *= dv;
                oB.x *= dv; oB.y *= dv; oB.z *= dv; oB.w *= dv;
            }
            ((uint4*)Y)[(long)gr * CG + cg] = pack8(oA, oB);
        }
        if (ALMODE) {
            int col0 = cg * 8;
            float4 sA = *(const float4*)&a_s[col0];
            float4 sB = *(const float4*)&a_s[col0 + 4];
            float4 dA = *(const float4*)&a_d[col0];
            float4 dB = *(const float4*)&a_d[col0 + 4];
            float s = aA.x * sA.x + aA.y * sA.y + aA.z * sA.z + aA.w * sA.w
                    + aB.x * sB.x + aB.y * sB.y + aB.z * sB.z + aB.w * sB.w;
            float d = aA.x * dA.x + aA.y * dA.y + aA.z * dA.z + aA.w * dA.w
                    + aB.x * dB.x + aB.y * dB.y + aB.z * dB.z + aB.w * dB.w;
            if (ALMODE == 1) {        // CG=8: head = cg>>2
                s += __shfl_xor_sync(0xffffffffu, s, 1);
                d += __shfl_xor_sync(0xffffffffu, d, 1);
                s += __shfl_xor_sync(0xffffffffu, s, 2);
                d += __shfl_xor_sync(0xffffffffu, d, 2);
                int head = cg >> 2;
                if (ok && (cg & 3) == 0) {
                    g_al[gr * 4 + head] = s;
                    g_al[gr * 4 + 2 + head] = d;
                }
            } else {                  // CG=4: head = cg>>1
                s += __shfl_xor_sync(0xffffffffu, s, 1);
                d += __shfl_xor_sync(0xffffffffu, d, 1);
                int head = cg >> 1;
                if (ok && (cg & 1) == 0) {
                    g_al[gr * 4 + head] = s;
                    g_al[gr * 4 + 2 + head] = d;
                }
            }
        }
    }
}

// ---------------- GCN gather: 4 lanes/node ----------------
__global__ void k_gcn_agg(const __half* __restrict__ h, __half* __restrict__ out,
                          const float* __restrict__ bias,
                          const float* __restrict__ bg, const float* __restrict__ bb,
                          const float* __restrict__ bm, const float* __restrict__ bv, int n) {
    int t = blockIdx.x * blockDim.x + threadIdx.x;
    int w = t >> 2, c = t & 3;
    if (w >= n) return;
    const uint4* h4 = (const uint4*)h;
    int deg = __ldg(&g_deg[w]);
    int base = w * MAXD;
    float dd = rsqrtf((float)(deg + 1));
    float4 accA, accB;
    unpack8(__ldg(&h4[(long)w * 4 + c]), accA, accB);  // self (pre-scaled)
#pragma unroll 8
    for (int j = 0; j < deg; ++j) {
        int s = __ldg(&g_csr[base + j]);
        float4 vA, vB;
        unpack8(__ldg(&h4[(long)s * 4 + c]), vA, vB);
        ADD4(accA, vA);
        ADD4(accB, vB);
    }
    const float4* b4 = (const float4*)bias;
    const float4* g4 = (const float4*)bg;
    const float4* bb4 = (const float4*)bb;
    const float4* m4 = (const float4*)bm;
    const float4* v4 = (const float4*)bv;
    float4 oA, oB;
    {
        float4 bi = __ldg(&b4[c * 2]), gg = __ldg(&g4[c * 2]), bbv = __ldg(&bb4[c * 2]);
        float4 mm = __ldg(&m4[c * 2]), vv = __ldg(&v4[c * 2]);
        oA.x = fmaxf((accA.x * dd + bi.x - mm.x) * (gg.x * rsqrtf(vv.x + EPSV)) + bbv.x, 0.f);
        oA.y = fmaxf((accA.y * dd + bi.y - mm.y) * (gg.y * rsqrtf(vv.y + EPSV)) + bbv.y, 0.f);
        oA.z = fmaxf((accA.z * dd + bi.z - mm.z) * (gg.z * rsqrtf(vv.z + EPSV)) + bbv.z, 0.f);
        oA.w = fmaxf((accA.w * dd + bi.w - mm.w) * (gg.w * rsqrtf(vv.w + EPSV)) + bbv.w, 0.f);
    }
    {
        float4 bi = __ldg(&b4[c * 2 + 1]), gg = __ldg(&g4[c * 2 + 1]), bbv = __ldg(&bb4[c * 2 + 1]);
        float4 mm = __ldg(&m4[c * 2 + 1]), vv = __ldg(&v4[c * 2 + 1]);
        oB.x = fmaxf((accB.x * dd + bi.x - mm.x) * (gg.x * rsqrtf(vv.x + EPSV)) + bbv.x, 0.f);
        oB.y = fmaxf((accB.y * dd + bi.y - mm.y) * (gg.y * rsqrtf(vv.y + EPSV)) + bbv.y, 0.f);
        oB.z = fmaxf((accB.z * dd + bi.z - mm.z) * (gg.z * rsqrtf(vv.z + EPSV)) + bbv.z, 0.f);
        oB.w = fmaxf((accB.w * dd + bi.w - mm.w) * (gg.w * rsqrtf(vv.w + EPSV)) + bbv.w, 0.f);
    }
    ((uint4*)out)[(long)w * 4 + c] = pack8(oA, oB);
}

// ---------------- GAT1 gather: 8 lanes/node (head = c>>2) ----------------
__global__ void k_gat1_agg(const __half* __restrict__ hg, __half* __restrict__ out,
                           const float* __restrict__ bias, int n) {
    int t = blockIdx.x * blockDim.x + threadIdx.x;
    int w = t >> 3, c = t & 7;
    if (w >= n) return;
    const uint4* hg4 = (const uint4*)hg;
    int deg = __ldg(&g_deg[w]);
    int base = w * MAXD;
    float ald0 = g_al[w * 4 + 2], ald1 = g_al[w * 4 + 3];
    float w0 = __expf(lrelu(g_al[w * 4 + 0] + ald0));
    float w1 = __expf(lrelu(g_al[w * 4 + 1] + ald1));
    float s0 = w0, s1 = w1;
    int head = c >> 2;
    float selfw = head ? w1 : w0;
    float4 accA, accB;
    unpack8(__ldg(&hg4[(long)w * 8 + c]), accA, accB);
    accA.x *= selfw; accA.y *= selfw; accA.z *= selfw; accA.w *= selfw;
    accB.x *= selfw; accB.y *= selfw; accB.z *= selfw; accB.w *= selfw;
#pragma unroll 4
    for (int j = 0; j < deg; ++j) {
        int s = __ldg(&g_csr[base + j]);
        float2 av = *(const float2*)&g_al[s * 4];
        float a0 = __expf(lrelu(av.x + ald0));
        float a1 = __expf(lrelu(av.y + ald1));
        s0 += a0; s1 += a1;
        float aw = head ? a1 : a0;
        float4 vA, vB;
        unpack8(__ldg(&hg4[(long)s * 8 + c]), vA, vB);
        FMA4(accA, vA, aw);
        FMA4(accB, vB, aw);
    }
    float iown = 0.5f / (head ? s1 : s0);
    float ioth = 0.5f / (head ? s0 : s1);
    float4 pA, pB;
    pA.x = __shfl_xor_sync(0xffffffffu, accA.x, 4);
    pA.y = __shfl_xor_sync(0xffffffffu, accA.y, 4);
    pA.z = __shfl_xor_sync(0xffffffffu, accA.z, 4);
    pA.w = __shfl_xor_sync(0xffffffffu, accA.w, 4);
    pB.x = __shfl_xor_sync(0xffffffffu, accB.x, 4);
    pB.y = __shfl_xor_sync(0xffffffffu, accB.y, 4);
    pB.z = __shfl_xor_sync(0xffffffffu, accB.z, 4);
    pB.w = __shfl_xor_sync(0xffffffffu, accB.w, 4);
    if (head == 0) {
        const float4* b4 = (const float4*)bias;
        float4 biA = __ldg(&b4[c * 2]), biB = __ldg(&b4[c * 2 + 1]);
        float4 oA, oB;
        oA.x = fmaxf(accA.x * iown + pA.x * ioth + biA.x, 0.f);
        oA.y = fmaxf(accA.y * iown + pA.y * ioth + biA.y, 0.f);
        oA.z = fmaxf(accA.z * iown + pA.z * ioth + biA.z, 0.f);
        oA.w = fmaxf(accA.w * iown + pA.w * ioth + biA.w, 0.f);
        oB.x = fmaxf(accB.x * iown + pB.x * ioth + biB.x, 0.f);
        oB.y = fmaxf(accB.y * iown + pB.y * ioth + biB.y, 0.f);
        oB.z = fmaxf(accB.z * iown + pB.z * ioth + biB.z, 0.f);
        oB.w = fmaxf(accB.w * iown + pB.w * ioth + biB.w, 0.f);
        ((uint4*)out)[(long)w * 4 + c] = pack8(oA, oB);
    }
}

// ---------------- GAT2 gather: 4 lanes/node (head = c>>1) + log_softmax ----------------
__global__ void k_gat2_agg(const __half* __restrict__ hg, float* __restrict__ out,
                           const float* __restrict__ bias, int n) {
    int t = blockIdx.x * blockDim.x + threadIdx.x;
    int w = t >> 2, c = t & 3;
    if (w >= n) return;
    const uint4* hg4 = (const uint4*)hg;
    int deg = __ldg(&g_deg[w]);
    int base = w * MAXD;
    float ald0 = g_al[w * 4 + 2], ald1 = g_al[w * 4 + 3];
    float w0 = __expf(lrelu(g_al[w * 4 + 0] + ald0));
    float w1 = __expf(lrelu(g_al[w * 4 + 1] + ald1));
    float s0 = w0, s1 = w1;
    int head = c >> 1;
    float selfw = head ? w1 : w0;
    float4 accA, accB;
    unpack8(__ldg(&hg4[(long)w * 4 + c]), accA, accB);
    accA.x *= selfw; accA.y *= selfw; accA.z *= selfw; accA.w *= selfw;
    accB.x *= selfw; accB.y *= selfw; accB.z *= selfw; accB.w *= selfw;
#pragma unroll 4
    for (int j = 0; j < deg; ++j) {
        int s = __ldg(&g_csr[base + j]);
        float2 av = *(const float2*)&g_al[s * 4];
        float a0 = __expf(lrelu(av.x + ald0));
        float a1 = __expf(lrelu(av.y + ald1));
        s0 += a0; s1 += a1;
        float aw = head ? a1 : a0;
        float4 vA, vB;
        unpack8(__ldg(&hg4[(long)s * 4 + c]), vA, vB);
        FMA4(accA, vA, aw);
        FMA4(accB, vB, aw);
    }
    float iown = 0.5f / (head ? s1 : s0);
    float ioth = 0.5f / (head ? s0 : s1);
    float4 pA, pB;
    pA.x = __shfl_xor_sync(0xffffffffu, accA.x, 2);
    pA.y = __shfl_xor_sync(0xffffffffu, accA.y, 2);
    pA.z = __shfl_xor_sync(0xffffffffu, accA.z, 2);
    pA.w = __shfl_xor_sync(0xffffffffu, accA.w, 2);
    pB.x = __shfl_xor_sync(0xffffffffu, accB.x, 2);
    pB.y = __shfl_xor_sync(0xffffffffu, accB.y, 2);
    pB.z = __shfl_xor_sync(0xffffffffu, accB.z, 2);
    pB.w = __shfl_xor_sync(0xffffffffu, accB.w, 2);
    int blk = c & 1;
    const float4* b4 = (const float4*)bias;
    float4 biA = __ldg(&b4[blk * 2]), biB = __ldg(&b4[blk * 2 + 1]);
    float4 vA, vB;
    vA.x = accA.x * iown + pA.x * ioth + biA.x;
    vA.y = accA.y * iown + pA.y * ioth + biA.y;
    vA.z = accA.z * iown + pA.z * ioth + biA.z;
    vA.w = accA.w * iown + pA.w * ioth + biA.w;
    vB.x = accB.x * iown + pB.x * ioth + biB.x;
    vB.y = accB.y * iown + pB.y * ioth + biB.y;
    vB.z = accB.z * iown + pB.z * ioth + biB.z;
    vB.w = accB.w * iown + pB.w * ioth + biB.w;
    float mx = fmaxf(fmaxf(vA.x, vA.y), fmaxf(vA.z, vA.w));
    mx = fmaxf(mx, fmaxf(fmaxf(vB.x, vB.y), fmaxf(vB.z, vB.w)));
    mx = fmaxf(mx, __shfl_xor_sync(0xffffffffu, mx, 1));
    float se = __expf(vA.x - mx) + __expf(vA.y - mx) + __expf(vA.z - mx) + __expf(vA.w - mx)
             + __expf(vB.x - mx) + __expf(vB.y - mx) + __expf(vB.z - mx) + __expf(vB.w - mx);
    se += __shfl_xor_sync(0xffffffffu, se, 1);
    float ls = __logf(se) + mx;
    if (head == 0) {
        float4 oA, oB;
        oA.x = vA.x - ls; oA.y = vA.y - ls; oA.z = vA.z - ls; oA.w = vA.w - ls;
        oB.x = vB.x - ls; oB.y = vB.y - ls; oB.z = vB.z - ls; oB.w = vB.w - ls;
        ((float4*)out)[(long)w * 4 + blk * 2] = oA;
        ((float4*)out)[(long)w * 4 + blk * 2 + 1] = oB;
    }
}

// ---------------- host ----------------
static inline int cdiv(long a, int b) { return (int)((a + b - 1) / b); }

extern "C" void kernel_launch(void* const* d_in, const int* in_sizes, int n_in,
                              void* d_out, int out_size) {
    const float* x   = (const float*)d_in[0];
    const int*   ei  = (const int*)d_in[1];
    const float* g1W = (const float*)d_in[2];
    const float* g1b = (const float*)d_in[3];
    const float* b1g = (const float*)d_in[4];
    const float* b1b = (const float*)d_in[5];
    const float* b1m = (const float*)d_in[6];
    const float* b1v = (const float*)d_in[7];
    const float* a1W = (const float*)d_in[8];
    const float* a1s = (const float*)d_in[9];
    const float* a1d = (const float*)d_in[10];
    const float* a1b = (const float*)d_in[11];
    const float* g2W = (const float*)d_in[12];
    const float* g2b = (const float*)d_in[13];
    const float* b2g = (const float*)d_in[14];
    const float* b2b = (const float*)d_in[15];
    const float* b2m = (const float*)d_in[16];
    const float* b2v = (const float*)d_in[17];
    const float* a2W = (const float*)d_in[18];
    const float* a2s = (const float*)d_in[19];
    const float* a2d = (const float*)d_in[20];
    const float* a2b = (const float*)d_in[21];

    int n = in_sizes[0] / FIN;
    int e = in_sizes[1] / 2;
    const int* src = ei;
    const int* dst = ei + e;

    __half *pA, *pB, *pWh;
    cudaGetSymbolAddress((void**)&pA, g_hA);
    cudaGetSymbolAddress((void**)&pB, g_hB);
    cudaGetSymbolAddress((void**)&pWh, g_Wh);
    int* pDeg;
    cudaGetSymbolAddress((void**)&pDeg, g_deg);

    const int B = 256;

    // ---- weight conversion + adjacency build ----
    cudaMemsetAsync(pDeg, 0, (size_t)n * sizeof(int));
    k_cvtW<<<32, 256>>>(g1W, a1W, g2W, a2W);
    k_scatter<<<cdiv(e, B), B>>>(src, dst, e);

    // ---- GCN1: tc GEMM K=128 F=32, fp32 input staged to half ----
    k_gemm_tc<FIN, FHID, 0, 1, 1><<<cdiv(n, 64), 256>>>(x, pWh + WOFF_G1, pA, nullptr, nullptr, n);
    k_gcn_agg<<<cdiv((long)n * 4, B), B>>>(pA, pB, g1b, b1g, b1b, b1m, b1v, n);

    // ---- GAT1: tc GEMM K=32 F=64 ----
    k_gemm_tc<FHID, 64, 1, 0, 0><<<cdiv(n, 64), 256>>>(pB, pWh + WOFF_A1, pA, a1s, a1d, n);
    k_gat1_agg<<<cdiv((long)n * 8, B), B>>>(pA, pB, a1b, n);

    // ---- GCN2: tc GEMM K=32 F=32 ----
    k_gemm_tc<FHID, FHID, 0, 1, 0><<<cdiv(n, 64), 256>>>(pB, pWh + WOFF_G2, pA, nullptr, nullptr, n);
    k_gcn_agg<<<cdiv((long)n * 4, B), B>>>(pA, pB, g2b, b2g, b2b, b2m, b2v, n);

    // ---- GAT2: tc GEMM K=32 F=32 + final log_softmax ----
    k_gemm_tc<FHID, FHID, 2, 0, 0><<<cdiv(n, 64), 256>>>(pB, pWh + WOFF_A2, pA, a2s, a2d, n);
    k_gat2_agg<<<cdiv((long)n * 4, B), B>>>(pA, (float*)d_out, a2b, n);
}